// round 5
// baseline (speedup 1.0000x reference)
#include <cuda_runtime.h>

// Heston Monte Carlo, 65536 paths x 512 steps.
// Inputs (metadata order): d_in[0] = Z_vol  [65536, 512, 2] f32
//                          d_in[1] = Z_price[65536, 512]    f32
// Output: concat(S, V), each [65536, 513] f32.

namespace {

constexpr int BATCH  = 65536;
constexpr int NSTEPS = 512;
constexpr int ROWLEN = NSTEPS + 1;   // 513
constexpr int BLOCK  = 128;          // paths per block
constexpr int CHUNK  = 32;           // time steps per staging chunk
constexpr int NCHUNK = NSTEPS / CHUNK;

constexpr float DT       = 1.0f / 512.0f;
constexpr float SQRT_DT  = 0.044194173824159216f;   // sqrt(1/512)
constexpr float V0C      = 0.055225f;               // 0.235^2
constexpr float THETA    = 0.04f;
constexpr float KAPPA    = 1.0f;
constexpr float SIGMA_V  = 2.0f;
constexpr float RHO      = -0.7f;
constexpr float RHO_PERP = 0.7141428428542850f;     // sqrt(1 - 0.49)
constexpr float S0       = 100.0f;

}  // namespace

__global__ void __launch_bounds__(BLOCK)
heston_kernel(const float* __restrict__ Zv,
              const float* __restrict__ Zp,
              float* __restrict__ out)
{
    // Padded rows: bank = (33*row + j) % 32 = (row + j) % 32 -> conflict-free
    // both for per-thread sequential reads and for broadcast-j access.
    __shared__ float sA[BLOCK][CHUNK + 1];  // stages Z_vol ch0, then reused for S
    __shared__ float sB[BLOCK][CHUNK + 1];  // stages Z_price,   then reused for V

    const int tid = threadIdx.x;
    const int b0  = blockIdx.x * BLOCK;

    float* __restrict__ Sout = out;
    float* __restrict__ Vout = out + (long long)BATCH * ROWLEN;

    // Column 0: S = S0, V = V0. (One scalar write per thread; negligible traffic.)
    {
        const long long r = (long long)(b0 + tid) * ROWLEN;
        Sout[r] = S0;
        Vout[r] = V0C;
    }

    float V    = V0C;
    float logS = 0.0f;

    for (int c = 0; c < NCHUNK; ++c) {
        const int t0 = c * CHUNK;

        // ---- Stage Z_vol channel 0: 128 rows x 64 interleaved floats -> 2048 float4 ----
        // Warp covers two contiguous 128B runs -> fully coalesced.
#pragma unroll
        for (int k = 0; k < 16; ++k) {
            const int idx = tid + k * BLOCK;        // 0..2047
            const int row = idx >> 4;               // path within block
            const int q   = idx & 15;               // float4 within row-chunk
            const float4 v = *reinterpret_cast<const float4*>(
                Zv + (long long)(b0 + row) * (2 * NSTEPS) + (t0 * 2 + q * 4));
            sA[row][2 * q]     = v.x;               // zv at step t0+2q
            sA[row][2 * q + 1] = v.z;               // zv at step t0+2q+1
        }

        // ---- Stage Z_price: 128 rows x 32 floats -> 1024 float4, coalesced ----
#pragma unroll
        for (int k = 0; k < 8; ++k) {
            const int idx = tid + k * BLOCK;        // 0..1023
            const int row = idx >> 3;
            const int q   = idx & 7;
            const float4 v = *reinterpret_cast<const float4*>(
                Zp + (long long)(b0 + row) * NSTEPS + (t0 + q * 4));
            sB[row][4 * q]     = v.x;
            sB[row][4 * q + 1] = v.y;
            sB[row][4 * q + 2] = v.z;
            sB[row][4 * q + 3] = v.w;
        }
        __syncthreads();

        // ---- Per-path recurrence over this chunk (smem reused in place) ----
#pragma unroll
        for (int j = 0; j < CHUNK; ++j) {
            const float zv = sA[tid][j];
            const float zp = sB[tid][j];

            const float Vpos = fmaxf(V, 0.0f);           // full truncation
            const float sq   = sqrtf(Vpos);
            float Vn = V + KAPPA * (THETA - Vpos) * DT
                         + SIGMA_V * sqrtf(Vpos * DT) * zv;
            Vn = fmaxf(Vn, 0.0f);

            const float dB = (RHO * SQRT_DT) * zv + (RHO_PERP * SQRT_DT) * zp;
            logS += -0.5f * Vpos * DT + sq * dB;         // cumulative log-price
            const float S = S0 * __expf(logS);

            sA[tid][j] = S;                              // same-thread overwrite: safe
            sB[tid][j] = Vn;
            V = Vn;
        }
        __syncthreads();

        // ---- Coalesced write-out: each warp writes one row's 32 contiguous floats ----
#pragma unroll
        for (int k = 0; k < 32; ++k) {
            const int idx = tid + k * BLOCK;        // 0..4095
            const int row = idx >> 5;
            const int col = idx & 31;
            const long long g = (long long)(b0 + row) * ROWLEN + 1 + t0 + col;
            Sout[g] = sA[row][col];
            Vout[g] = sB[row][col];
        }
        __syncthreads();  // protect smem before next chunk's staging overwrites it
    }
}

extern "C" void kernel_launch(void* const* d_in, const int* in_sizes, int n_in,
                              void* d_out, int out_size) {
    (void)in_sizes; (void)n_in; (void)out_size;
    const float* Zv = (const float*)d_in[0];
    const float* Zp = (const float*)d_in[1];
    float* out = (float*)d_out;
    heston_kernel<<<BATCH / BLOCK, BLOCK>>>(Zv, Zp, out);
}

// round 9
// speedup vs baseline: 1.9145x; 1.9145x over previous
#include <cuda_runtime.h>

// Heston Monte Carlo, 65536 paths x 512 steps.
// d_in[0] = Z_vol [65536, 512, 2] f32 (channel-interleaved), d_in[1] = Z_price [65536, 512] f32
// d_out = concat(S, V), each [65536, 513] f32.

namespace {

constexpr int BATCH  = 65536;
constexpr int NSTEPS = 512;
constexpr int ROWLEN = NSTEPS + 1;     // 513
constexpr int BLOCK  = 64;             // paths per block
constexpr int CHUNK  = 16;             // time steps per staged chunk
constexpr int NCHUNK = NSTEPS / CHUNK; // 32

constexpr float DT       = 1.0f / 512.0f;
constexpr float SQRT_DT  = 0.044194173824159216f;  // sqrt(1/512)
constexpr float V0C      = 0.055225f;              // 0.235^2
constexpr float S0F      = 100.0f;

constexpr float KTDT  = 1.0f * 0.04f * DT;         // KAPPA*THETA*dt
constexpr float NKDT  = -1.0f * DT;                // -KAPPA*dt
constexpr float CSV   = 2.0f * SQRT_DT;            // SIGMA_V*sqrt(dt)
constexpr float RSD   = -0.7f * SQRT_DT;           // RHO*sqrt(dt)
constexpr float RPSD  = 0.7141428428542850f * SQRT_DT; // sqrt(1-rho^2)*sqrt(dt)
constexpr float NHDT  = -0.5f * DT;
constexpr float LOG2E   = 1.4426950408889634f;
constexpr float LOG2S0  = 6.6438561897747395f;     // log2(100)

}  // namespace

__device__ __forceinline__ float sqrt_approx(float x) {
    float r; asm("sqrt.approx.f32 %0, %1;" : "=f"(r) : "f"(x)); return r;
}
__device__ __forceinline__ float ex2_approx(float x) {
    float r; asm("ex2.approx.f32 %0, %1;" : "=f"(r) : "f"(x)); return r;
}
__device__ __forceinline__ void cp16(unsigned dst, const void* src) {
    asm volatile("cp.async.cg.shared.global [%0], [%1], 16;\n"
                 :: "r"(dst), "l"(src) : "memory");
}
__device__ __forceinline__ void cp_commit() {
    asm volatile("cp.async.commit_group;\n" ::: "memory");
}
__device__ __forceinline__ void cp_wait1() {
    asm volatile("cp.async.wait_group 1;\n" ::: "memory");
}

__global__ void __launch_bounds__(BLOCK, 7)
heston_kernel(const float* __restrict__ Zv,
              const float* __restrict__ Zp,
              float* __restrict__ out)
{
    // Zv chunks: 128B rows, slot swizzle q^(row&7). Compute/writeout LDS.128 is
    // phase-conflict-free (each 8-lane phase covers 8 distinct bank-quads).
    // Reused in place for results (S0,V0,S1,V1) per 16B chunk.
    __shared__ float4 zv[2][BLOCK][8];
    // Zp chunks: 64B rows (4 x 16B), slot swizzle q^((row>>2)&3); cp.async dst
    // stays 16B-aligned; compute LDS.64 has <=2-way conflicts.
    __shared__ float4 zp[2][BLOCK][4];

    const int tid = threadIdx.x;
    const int b0  = blockIdx.x * BLOCK;
    const int r7  = tid & 7;
    const int r23 = (tid >> 2) & 3;

    float* __restrict__ Sout = out;
    float* __restrict__ Vout = out + (size_t)BATCH * ROWLEN;

    // Column 0: S = S0, V = V0.
    {
        const size_t g = (size_t)(b0 + tid) * ROWLEN;
        Sout[g] = S0F;
        Vout[g] = V0C;
    }

    const char* zv_gbase = (const char*)Zv + (size_t)b0 * (2 * NSTEPS * 4);
    const char* zp_gbase = (const char*)Zp + (size_t)b0 * (NSTEPS * 4);

    // Stage Zv chunk (64 rows x 128B = 8 cp/thread) + Zp chunk (64 rows x 64B =
    // 4 cp/thread) into buffer bi_, ONE commit group per chunk.
#define STAGE(c_, bi_)                                                             \
    do {                                                                           \
        _Pragma("unroll")                                                          \
        for (int k = 0; k < 8; ++k) {                                              \
            const int idx = tid + BLOCK * k;      /* 0..511 */                     \
            const int row = idx >> 3;                                              \
            const int q   = idx & 7;                                               \
            cp16((unsigned)__cvta_generic_to_shared(&zv[bi_][row][q ^ (row & 7)]), \
                 zv_gbase + (size_t)row * (2 * NSTEPS * 4) + (size_t)(c_) * 128 + q * 16); \
        }                                                                          \
        _Pragma("unroll")                                                          \
        for (int k = 0; k < 4; ++k) {                                              \
            const int idx = tid + BLOCK * k;      /* 0..255 */                     \
            const int row = idx >> 2;                                              \
            const int q   = idx & 3;                                               \
            cp16((unsigned)__cvta_generic_to_shared(&zp[bi_][row][q ^ ((row >> 2) & 3)]), \
                 zp_gbase + (size_t)row * (NSTEPS * 4) + (size_t)(c_) * 64 + q * 16); \
        }                                                                          \
        cp_commit();                                                               \
    } while (0)

    // ---- prologue: chunks 0 and 1 in flight (groups 0,1) ----
    STAGE(0, 0);
    STAGE(1, 1);

    float V    = V0C;
    float logS = 0.0f;

    for (int c = 0; c < NCHUNK; ++c) {
        const int p = c & 1;

        cp_wait1();          // group for chunk c done (c+1 may still fly)
        __syncthreads();     // visible to whole block

        // ---- 16 steps; results overwrite the consumed zv chunk in place ----
        const float* zprow = (const float*)&zp[p][tid][0];
#pragma unroll
        for (int j2 = 0; j2 < 8; ++j2) {
            const int slot = j2 ^ r7;
            const float4 zz = zv[p][tid][slot];        // (zv_{2j2}, ch1, zv_{2j2+1}, ch1)
            const int zslot = (j2 >> 1) ^ r23;
            const float2 zpp = *reinterpret_cast<const float2*>(
                zprow + 4 * zslot + 2 * (j2 & 1));     // (zp_{2j2}, zp_{2j2+1})
            float4 res;

            {   // step 2*j2
                const float Vpos = fmaxf(V, 0.0f);
                const float sq   = sqrt_approx(Vpos);
                float Vn = fmaf(NKDT, Vpos, V + KTDT);
                Vn = fmaf(CSV * sq, zz.x, Vn);
                Vn = fmaxf(Vn, 0.0f);
                const float dB = fmaf(RSD, zz.x, RPSD * zpp.x);
                logS = fmaf(sq, dB, fmaf(NHDT, Vpos, logS));
                res.x = ex2_approx(fmaf(logS, LOG2E, LOG2S0));  // S after step 2j2
                res.y = Vn;
                V = Vn;
            }
            {   // step 2*j2 + 1
                const float Vpos = fmaxf(V, 0.0f);
                const float sq   = sqrt_approx(Vpos);
                float Vn = fmaf(NKDT, Vpos, V + KTDT);
                Vn = fmaf(CSV * sq, zz.z, Vn);
                Vn = fmaxf(Vn, 0.0f);
                const float dB = fmaf(RSD, zz.z, RPSD * zpp.y);
                logS = fmaf(sq, dB, fmaf(NHDT, Vpos, logS));
                res.z = ex2_approx(fmaf(logS, LOG2E, LOG2S0));  // S after step 2j2+1
                res.w = Vn;
                V = Vn;
            }
            zv[p][tid][slot] = res;   // same-thread in-place overwrite: safe
        }
        __syncthreads();

        // ---- cooperative write-out (32 contiguous-ish floats per row-chunk) ----
        {
            const int t0 = c * CHUNK;
#pragma unroll
            for (int k = 0; k < 8; ++k) {
                const int idx = tid + BLOCK * k;      // 0..511
                const int row = idx >> 3;
                const int l   = idx & 7;
                const float4 r = zv[p][row][l ^ (row & 7)];
                const size_t g = (size_t)(b0 + row) * ROWLEN + (t0 + 1 + 2 * l);
                Sout[g]     = r.x;
                Sout[g + 1] = r.z;
                Vout[g]     = r.y;
                Vout[g + 1] = r.w;
            }
        }
        __syncthreads();     // buffer p fully drained before restage

        // restage into freed buffer; exactly one commit per iteration so the
        // group count stays aligned with c (wait_group 1 above stays valid)
        if (c + 2 < NCHUNK) STAGE(c + 2, p);
        else                cp_commit();
    }
#undef STAGE
}

extern "C" void kernel_launch(void* const* d_in, const int* in_sizes, int n_in,
                              void* d_out, int out_size) {
    (void)in_sizes; (void)n_in; (void)out_size;
    heston_kernel<<<BATCH / BLOCK, BLOCK>>>(
        (const float*)d_in[0], (const float*)d_in[1], (float*)d_out);
}